// round 7
// baseline (speedup 1.0000x reference)
#include <cuda_runtime.h>
#include <math.h>

#define LAYERS 6
#define DIM    16
#define NH     8
#define NBATCH 16
#define BOTD   26
#define NTOK   50625
#define TPB    256
#define SPAN   (TPB * 2)
#define NCH    99
#define LN_EPS 1e-5f

typedef unsigned long long u64;

// ---------------- static scratch ----------------
__device__ __align__(16) float4 g_x4[4][(size_t)NBATCH * NTOK];
__device__ __align__(16) float4 g_rot[NTOK];
__device__ float g_part[2][(size_t)NBATCH * NCH * 40];   // buf0=q, buf1=k partials
__device__ __align__(16) float c_Wqkv[LAYERS][DIM * 96];
__device__ __align__(16) float c_bqkv[LAYERS][96];
__device__ __align__(16) float c_Wff1[LAYERS][DIM * 64];
__device__ __align__(16) float c_bff1[LAYERS][64];
__device__ __align__(16) float c_M1[LAYERS][256];
__device__ __align__(16) float c_M2[LAYERS][256];
__device__ __align__(16) float c_c0[LAYERS][16];
__device__ __align__(16) float c_w2o[64];
__device__ float c_cout;

// ---------------- f32x2 packed helpers ----------------
__device__ __forceinline__ u64 pack2(float x, float y) {
    u64 r; asm("mov.b64 %0, {%1, %2};" : "=l"(r) : "f"(x), "f"(y)); return r;
}
__device__ __forceinline__ void unpack2(u64 v, float &x, float &y) {
    asm("mov.b64 {%0, %1}, %2;" : "=f"(x), "=f"(y) : "l"(v));
}
__device__ __forceinline__ u64 ffma2(u64 a, u64 b, u64 c) {
    u64 r; asm("fma.rn.f32x2 %0, %1, %2, %3;" : "=l"(r) : "l"(a), "l"(b), "l"(c)); return r;
}
__device__ __forceinline__ u64 mul2(u64 a, u64 b) {
    u64 r; asm("mul.rn.f32x2 %0, %1, %2;" : "=l"(r) : "l"(a), "l"(b)); return r;
}
__device__ __forceinline__ u64 add2(u64 a, u64 b) {
    u64 r; asm("add.rn.f32x2 %0, %1, %2;" : "=l"(r) : "l"(a), "l"(b)); return r;
}

// ---------------- pair load/store ----------------
__device__ __forceinline__ void load16pair(size_t i0, size_t i1, int valid1, u64 xp[16]) {
    #pragma unroll
    for (int p = 0; p < 4; p++) {
        float4 a = g_x4[p][i0];
        float4 b = valid1 ? g_x4[p][i1] : make_float4(0.f, 0.f, 0.f, 0.f);
        xp[p * 4 + 0] = pack2(a.x, b.x); xp[p * 4 + 1] = pack2(a.y, b.y);
        xp[p * 4 + 2] = pack2(a.z, b.z); xp[p * 4 + 3] = pack2(a.w, b.w);
    }
}
__device__ __forceinline__ void store16pair(size_t i0, size_t i1, int valid1, const u64 xp[16]) {
    #pragma unroll
    for (int p = 0; p < 4; p++) {
        float4 a, b;
        unpack2(xp[p * 4 + 0], a.x, b.x); unpack2(xp[p * 4 + 1], a.y, b.y);
        unpack2(xp[p * 4 + 2], a.z, b.z); unpack2(xp[p * 4 + 3], a.w, b.w);
        g_x4[p][i0] = a;
        if (valid1) g_x4[p][i1] = b;
    }
}

// packed LN: z = (x-mean)*rsqrt(var+eps) per lane (token)
__device__ __forceinline__ void lnz_pair(const u64 xp[16], u64 zp[16]) {
    const u64 C16  = pack2(0.0625f, 0.0625f);
    const u64 NEG1 = pack2(-1.f, -1.f);
    u64 mp = xp[0];
    #pragma unroll
    for (int d = 1; d < 16; d++) mp = add2(mp, xp[d]);
    mp = mul2(mp, C16);
    u64 vp = 0ull;
    #pragma unroll
    for (int d = 0; d < 16; d++) { u64 t = ffma2(mp, NEG1, xp[d]); vp = ffma2(t, t, vp); }
    vp = mul2(vp, C16);
    float va, vb;
    unpack2(vp, va, vb);
    u64 ip = pack2(rsqrtf(va + LN_EPS), rsqrtf(vb + LN_EPS));
    #pragma unroll
    for (int d = 0; d < 16; d++) zp[d] = mul2(ffma2(mp, NEG1, xp[d]), ip);
}

__device__ __forceinline__ float gelu_exact(float t) {
    float xx = t * 0.70710678118654752440f;
    float a  = fabsf(xx);
    float u  = __fdividef(1.f, fmaf(0.3275911f, a, 1.f));
    float p  = u * (0.254829592f + u * (-0.284496736f + u * (1.421413741f +
               u * (-1.453152027f + u * 1.061405429f))));
    float er = 1.f - p * __expf(-a * a);
    er = copysignf(er, xx);
    return 0.5f * t * (1.f + er);
}

// per-head immediate warp reduce of (s,w0..w3) into sred
__device__ __forceinline__ void head_reduce(float (*sred)[40], int wid, int lane, int h,
                                            float s, float w0, float w1, float w2, float w3) {
    const unsigned FULL = 0xffffffffu;
    #pragma unroll
    for (int off = 16; off; off >>= 1) {
        s  += __shfl_xor_sync(FULL, s,  off);
        w0 += __shfl_xor_sync(FULL, w0, off);
        w1 += __shfl_xor_sync(FULL, w1, off);
        w2 += __shfl_xor_sync(FULL, w2, off);
        w3 += __shfl_xor_sync(FULL, w3, off);
    }
    if (lane == 0) {
        sred[wid][h * 5 + 0] = s;
        sred[wid][h * 5 + 1] = w0; sred[wid][h * 5 + 2] = w1;
        sred[wid][h * 5 + 3] = w2; sred[wid][h * 5 + 4] = w3;
    }
}

__device__ __forceinline__ void finish_partials(float (*sred)[40], int b, int chunk, int buf) {
    __syncthreads();
    if (threadIdx.x < 40) {
        float acc = 0.f;
        #pragma unroll
        for (int w = 0; w < TPB / 32; w++) acc += sred[w][threadIdx.x];
        g_part[buf][(size_t)(b * NCH + chunk) * 40 + threadIdx.x] = acc;
    }
}

// prologue merge of this batch's partials -> normalized sg[32]
__device__ __forceinline__ void reduce_global(int b, int buf, float sg[32]) {
    __shared__ float spart[6][40];
    int tid = threadIdx.x;
    if (tid < 240) {
        int sub = tid / 40, f = tid % 40;
        float s = 0.f;
        for (int c = sub; c < NCH; c += 6)
            s += g_part[buf][(size_t)(b * NCH + c) * 40 + f];
        spart[sub][f] = s;
    }
    __syncthreads();
    if (tid < 8) {
        float s = 0.f;
        #pragma unroll
        for (int k = 0; k < 6; k++) s += spart[k][tid * 5];
        float inv = 1.f / s;
        #pragma unroll
        for (int j = 0; j < 4; j++) {
            float w = 0.f;
            #pragma unroll
            for (int k = 0; k < 6; k++) w += spart[k][tid * 5 + 1 + j];
            sg[tid * 4 + j] = w * inv;
        }
    }
    __syncthreads();
}

// pass-A (q logits + rotary aggr) over a token pair; dup'd weights; per-head reduce
__device__ __forceinline__ void passA_pair(const u64 zq[16], float4 rt0, float4 rt1, float v1,
                                           const float *Wqdup, const float *bqdup, const float *wql,
                                           float (*sred)[40], int wid, int lane) {
    #pragma unroll
    for (int h = 0; h < NH; h++) {
        u64 qp0 = *(const u64 *)(bqdup + h * 8);
        u64 qp1 = *(const u64 *)(bqdup + h * 8 + 2);
        u64 qp2 = *(const u64 *)(bqdup + h * 8 + 4);
        u64 qp3 = *(const u64 *)(bqdup + h * 8 + 6);
        #pragma unroll
        for (int d = 0; d < 16; d++) {
            ulonglong2 wA = *(const ulonglong2 *)(Wqdup + d * 64 + h * 8);
            ulonglong2 wB = *(const ulonglong2 *)(Wqdup + d * 64 + h * 8 + 4);
            qp0 = ffma2(zq[d], wA.x, qp0); qp1 = ffma2(zq[d], wA.y, qp1);
            qp2 = ffma2(zq[d], wB.x, qp2); qp3 = ffma2(zq[d], wB.y, qp3);
        }
        float q00, q10, q01, q11, q02, q12, q03, q13;
        unpack2(qp0, q00, q10); unpack2(qp1, q01, q11);
        unpack2(qp2, q02, q12); unpack2(qp3, q03, q13);
        float l0 = (q00 * wql[0] + q01 * wql[1] + q02 * wql[2] + q03 * wql[3]) * 0.5f;
        float l1 = (q10 * wql[0] + q11 * wql[1] + q12 * wql[2] + q13 * wql[3]) * 0.5f;
        float p0 = __expf(l0), p1 = __expf(l1) * v1;
        float s  = p0 + p1;
        float w0 = p0 * (q00 * rt0.x - q01 * rt0.y) + p1 * (q10 * rt1.x - q11 * rt1.y);
        float w1 = p0 * (q01 * rt0.x + q00 * rt0.y) + p1 * (q11 * rt1.x + q10 * rt1.y);
        float w2 = p0 * (q02 * rt0.z - q03 * rt0.w) + p1 * (q12 * rt1.z - q13 * rt1.w);
        float w3 = p0 * (q03 * rt0.z + q02 * rt0.w) + p1 * (q13 * rt1.z + q12 * rt1.w);
        head_reduce(sred, wid, lane, h, s, w0, w1, w2, w3);
    }
}

// ---------------- kernels ----------------
__global__ void k_rot() {
    int n = blockIdx.x * blockDim.x + threadIdx.x;
    if (n >= NTOK) return;
    float t = (float)n;
    float s0, c0, s1, c1;
    sincosf(t * (float)M_PI, &s0, &c0);
    sincosf(t * (float)(5.0 * M_PI), &s1, &c1);
    g_rot[n] = make_float4(c0, s0, c1, s1);
}

__global__ void k_prep(const float *__restrict__ ln1g, const float *__restrict__ ln1b,
                       const float *__restrict__ Wqkv,
                       const float *__restrict__ ln2g, const float *__restrict__ ln2b,
                       const float *__restrict__ Wff1, const float *__restrict__ bff1,
                       const float *__restrict__ Wr, const float *__restrict__ br,
                       const float *__restrict__ Wo, const float *__restrict__ bo,
                       const float *__restrict__ Wff2, const float *__restrict__ bff2,
                       const float *__restrict__ Wout, const float *__restrict__ bout) {
    int tid = threadIdx.x;
    for (int i = tid; i < LAYERS * DIM * 96; i += blockDim.x) {
        int l = i / (DIM * 96), r = i % (DIM * 96), d = r / 96;
        c_Wqkv[l][r] = ln1g[l * 16 + d] * Wqkv[i];
    }
    for (int i = tid; i < LAYERS * 96; i += blockDim.x) {
        int l = i / 96, c = i % 96;
        float s = 0.f;
        for (int d = 0; d < 16; d++) s += ln1b[l * 16 + d] * Wqkv[(l * 16 + d) * 96 + c];
        c_bqkv[l][c] = s;
    }
    for (int i = tid; i < LAYERS * DIM * 64; i += blockDim.x) {
        int l = i / (DIM * 64), r = i % (DIM * 64), d = r / 64;
        c_Wff1[l][r] = ln2g[l * 16 + d] * Wff1[i];
    }
    for (int i = tid; i < LAYERS * 64; i += blockDim.x) {
        int l = i / 64, c = i % 64;
        float s = bff1[i];
        for (int d = 0; d < 16; d++) s += ln2b[l * 16 + d] * Wff1[(l * 16 + d) * 64 + c];
        c_bff1[l][c] = s;
    }
    __syncthreads();
    for (int i = tid; i < LAYERS * 256; i += blockDim.x) {
        int l = i >> 8, r = i & 255, d = r >> 4, e = r & 15;
        float s = 0.f;
        for (int c = 0; c < 32; c++) s += c_Wqkv[l][d * 96 + c] * Wo[l * 512 + c * 16 + e];
        c_M1[l][r] = s;
        int h = d >> 1, ii = d & 1;
        float s2 = 0.f;
        for (int j = 0; j < 4; j++) s2 += Wr[l * 8 + ii * 4 + j] * Wo[l * 512 + (h * 4 + j) * 16 + e];
        c_M2[l][r] = s2;
    }
    for (int i = tid; i < LAYERS * 16; i += blockDim.x) {
        int l = i >> 4, e = i & 15;
        float s = bo[l * 16 + e];
        for (int c = 0; c < 32; c++) s += c_bqkv[l][c] * Wo[l * 512 + c * 16 + e];
        for (int h = 0; h < NH; h++)
            for (int j = 0; j < 4; j++) s += br[l * 4 + j] * Wo[l * 512 + (h * 4 + j) * 16 + e];
        c_c0[l][e] = s;
    }
    for (int i = tid; i < 64; i += blockDim.x) {
        float s = 0.f;
        for (int e = 0; e < 16; e++) s += Wff2[(LAYERS - 1) * 1024 + i * 16 + e] * Wout[e];
        c_w2o[i] = s;
    }
    if (tid == 0) {
        float s = bout[0];
        for (int e = 0; e < 16; e++) s += bff2[(LAYERS - 1) * 16 + e] * Wout[e];
        c_cout = s;
    }
}

// embedding + fused pass-A of layer 0
__global__ void __launch_bounds__(TPB, 3) k_embed(
    const float *__restrict__ corr, const float *__restrict__ Wemb, const float *__restrict__ bemb,
    const float *__restrict__ wqlog) {
    __shared__ __align__(16) float sWembdup[BOTD * 32];
    __shared__ __align__(16) float sbembdup[32], sbqdup[64];
    __shared__ float swql[4];
    __shared__ __align__(16) float sWqdup[DIM * 64];
    __shared__ float sred[TPB / 32][40];
    int tid = threadIdx.x, b = blockIdx.y;
    int wid = tid >> 5, lane = tid & 31;
    for (int i = tid; i < BOTD * 32; i += TPB) sWembdup[i] = Wemb[(i >> 5) * 16 + ((i & 31) >> 1)];
    for (int i = tid; i < 32; i += TPB) sbembdup[i] = bemb[i >> 1];
    for (int i = tid; i < DIM * 64; i += TPB) sWqdup[i] = c_Wqkv[0][(i >> 6) * 96 + ((i & 63) >> 1)];
    for (int i = tid; i < 64; i += TPB) sbqdup[i] = c_bqkv[0][i >> 1];
    if (tid < 4) swql[tid] = wqlog[tid];
    __syncthreads();

    int n0 = blockIdx.x * SPAN + tid, n1 = n0 + TPB;
    int valid1 = n1 < NTOK;
    float v1 = valid1 ? 1.f : 0.f;
    const float *cb = corr + (size_t)b * BOTD * NTOK;

    u64 xp[16];
    #pragma unroll
    for (int e = 0; e < 16; e++) xp[e] = *(const u64 *)(sbembdup + e * 2);
    #pragma unroll 2
    for (int c = 0; c < BOTD; c++) {
        float c0 = fmaxf(cb[c * NTOK + n0], 0.f);
        float c1 = valid1 ? fmaxf(cb[c * NTOK + n1], 0.f) : 0.f;
        u64 cp = pack2(c0, c1);
        #pragma unroll
        for (int k = 0; k < 8; k++) {
            ulonglong2 w = *(const ulonglong2 *)(sWembdup + c * 32 + k * 4);
            xp[2 * k]     = ffma2(cp, w.x, xp[2 * k]);
            xp[2 * k + 1] = ffma2(cp, w.y, xp[2 * k + 1]);
        }
    }
    size_t base = (size_t)b * NTOK;
    store16pair(base + n0, base + n1, valid1, xp);
    float4 rt0 = g_rot[n0];
    float4 rt1 = valid1 ? g_rot[n1] : make_float4(1, 0, 1, 0);

    u64 zq[16];
    lnz_pair(xp, zq);
    passA_pair(zq, rt0, rt1, v1, sWqdup, sbqdup, swql, sred, wid, lane);
    finish_partials(sred, b, blockIdx.x, 0);
}

// pass-B: merge q-partials -> gq; k logits -> k-partials
__global__ void __launch_bounds__(TPB, 4) k_passB(
    const float *__restrict__ wklog_all, int layer) {
    __shared__ float swkl[2], sgq[32];
    __shared__ __align__(16) float sbkdup[64];
    __shared__ __align__(16) float sWkdup[DIM * 64];
    __shared__ float sred[TPB / 32][40];
    int tid = threadIdx.x, b = blockIdx.y;
    int wid = tid >> 5, lane = tid & 31;
    for (int i = tid; i < DIM * 64; i += TPB) sWkdup[i] = c_Wqkv[layer][(i >> 6) * 96 + 32 + ((i & 63) >> 1)];
    for (int i = tid; i < 64; i += TPB) sbkdup[i] = c_bqkv[layer][32 + (i >> 1)];
    if (tid < 2) swkl[tid] = wklog_all[layer * 2 + tid];
    reduce_global(b, 0, sgq);

    int n0 = blockIdx.x * SPAN + tid, n1 = n0 + TPB;
    int valid1 = n1 < NTOK;
    float v1 = valid1 ? 1.f : 0.f;
    size_t base = (size_t)b * NTOK;
    u64 zp[16];
    {
        u64 xp[16];
        load16pair(base + n0, base + n1, valid1, xp);
        lnz_pair(xp, zp);
    }
    float4 rt0 = g_rot[n0];
    float4 rt1 = valid1 ? g_rot[n1] : make_float4(1, 0, 1, 0);

    #pragma unroll
    for (int h = 0; h < NH; h++) {
        u64 kp0 = *(const u64 *)(sbkdup + h * 8);
        u64 kp1 = *(const u64 *)(sbkdup + h * 8 + 2);
        u64 kp2 = *(const u64 *)(sbkdup + h * 8 + 4);
        u64 kp3 = *(const u64 *)(sbkdup + h * 8 + 6);
        #pragma unroll
        for (int d = 0; d < 16; d++) {
            ulonglong2 wA = *(const ulonglong2 *)(sWkdup + d * 64 + h * 8);
            ulonglong2 wB = *(const ulonglong2 *)(sWkdup + d * 64 + h * 8 + 4);
            kp0 = ffma2(zp[d], wA.x, kp0); kp1 = ffma2(zp[d], wA.y, kp1);
            kp2 = ffma2(zp[d], wB.x, kp2); kp3 = ffma2(zp[d], wB.y, kp3);
        }
        float k00, k10, k01, k11, k02, k12, k03, k13;
        unpack2(kp0, k00, k10); unpack2(kp1, k01, k11);
        unpack2(kp2, k02, k12); unpack2(kp3, k03, k13);
        float g0 = sgq[h * 4 + 0], g1 = sgq[h * 4 + 1], g2 = sgq[h * 4 + 2], g3 = sgq[h * 4 + 3];
        float l0 = ((k00 * g0 + k01 * g1) * swkl[0] + (k02 * g2 + k03 * g3) * swkl[1]) * 0.5f;
        float l1 = ((k10 * g0 + k11 * g1) * swkl[0] + (k12 * g2 + k13 * g3) * swkl[1]) * 0.5f;
        float p0 = __expf(l0), p1 = __expf(l1) * v1;
        float s  = p0 + p1;
        float w0 = p0 * (k00 * rt0.x - k01 * rt0.y) + p1 * (k10 * rt1.x - k11 * rt1.y);
        float w1 = p0 * (k01 * rt0.x + k00 * rt0.y) + p1 * (k11 * rt1.x + k10 * rt1.y);
        float w2 = p0 * (k02 * rt0.z - k03 * rt0.w) + p1 * (k12 * rt1.z - k13 * rt1.w);
        float w3 = p0 * (k03 * rt0.z + k02 * rt0.w) + p1 * (k13 * rt1.z + k12 * rt1.w);
        head_reduce(sred, wid, lane, h, s, w0, w1, w2, w3);
    }
    finish_partials(sred, b, blockIdx.x, 1);
}

// pass-C: merge k-partials -> gk; folded attn tail; FF; next pass-A (or output)
__global__ void __launch_bounds__(TPB, 3) k_passC(
    const float *__restrict__ Wff2_all, const float *__restrict__ bff2_all,
    const float *__restrict__ wqlog_all, const float *__restrict__ Wout,
    float *__restrict__ out, int layer, int last) {
    __shared__ float sgk[32], swqlN[4], sWout[16], scout;
    __shared__ __align__(16) float sWu[256], sMdup[512], scdup[32];
    __shared__ __align__(16) float sbff1dup[128], sbff2dup[32], sbqNdup[64], sw2o[64];
    __shared__ __align__(16) float sWff1dup[2048], sWff2dup[2048], sWqNdup[1024];
    __shared__ float sred[TPB / 32][40];
    int tid = threadIdx.x, b = blockIdx.y;
    int wid = tid >> 5, lane = tid & 31;

    for (int i = tid; i < 2048; i += TPB)
        sWff1dup[i] = c_Wff1[layer][(i >> 7) * 64 + ((i & 127) >> 1)];
    for (int i = tid; i < 128; i += TPB) sbff1dup[i] = c_bff1[layer][i >> 1];
    if (!last) {
        int nl = layer + 1;
        for (int i = tid; i < 2048; i += TPB)
            sWff2dup[i] = Wff2_all[layer * 1024 + (i >> 5) * 16 + ((i & 31) >> 1)];
        for (int i = tid; i < 32; i += TPB) sbff2dup[i] = bff2_all[layer * 16 + (i >> 1)];
        for (int i = tid; i < 1024; i += TPB)
            sWqNdup[i] = c_Wqkv[nl][(i >> 6) * 96 + ((i & 63) >> 1)];
        for (int i = tid; i < 64; i += TPB) sbqNdup[i] = c_bqkv[nl][i >> 1];
        if (tid < 4) swqlN[tid] = wqlog_all[nl * 4 + tid];
    } else {
        for (int i = tid; i < 64; i += TPB) sw2o[i] = c_w2o[i];
        for (int i = tid; i < 16; i += TPB) sWout[i] = Wout[i];
        if (tid == 0) scout = c_cout;
    }
    reduce_global(b, 1, sgk);

    // fold gk: M = M1 + (Wv'.gk-pairsum)@M2 (dup'd), c = c0 + bu@M2 (dup'd)
    {
        int d = tid >> 4, m = tid & 15;
        const float *wv = &c_Wqkv[layer][d * 96 + 64];
        sWu[tid] = wv[2 * m] * sgk[2 * m] + wv[2 * m + 1] * sgk[2 * m + 1];
    }
    __syncthreads();
    {
        int d = tid >> 4, e = tid & 15;
        float acc = c_M1[layer][tid];
        #pragma unroll 4
        for (int m = 0; m < 16; m++) acc = fmaf(sWu[d * 16 + m], c_M2[layer][m * 16 + e], acc);
        sMdup[d * 32 + 2 * e] = acc;
        sMdup[d * 32 + 2 * e + 1] = acc;
    }
    if (tid < 16) {
        float acc = c_c0[layer][tid];
        #pragma unroll 4
        for (int m = 0; m < 16; m++) {
            float bu = c_bqkv[layer][64 + 2 * m] * sgk[2 * m] + c_bqkv[layer][64 + 2 * m + 1] * sgk[2 * m + 1];
            acc = fmaf(bu, c_M2[layer][m * 16 + tid], acc);
        }
        scdup[2 * tid] = acc; scdup[2 * tid + 1] = acc;
    }
    __syncthreads();

    int n0 = blockIdx.x * SPAN + tid, n1 = n0 + TPB;
    int valid1 = n1 < NTOK;
    float v1 = valid1 ? 1.f : 0.f;
    size_t base = (size_t)b * NTOK;

    u64 xp[16], zp[16];
    load16pair(base + n0, base + n1, valid1, xp);
    lnz_pair(xp, zp);

    // attn tail: x += z@M + c
    #pragma unroll
    for (int e = 0; e < 16; e++) xp[e] = add2(xp[e], *(const u64 *)(scdup + 2 * e));
    #pragma unroll
    for (int d = 0; d < 16; d++) {
        #pragma unroll
        for (int k = 0; k < 8; k++) {
            ulonglong2 w = *(const ulonglong2 *)(sMdup + d * 32 + k * 4);
            xp[2 * k]     = ffma2(zp[d], w.x, xp[2 * k]);
            xp[2 * k + 1] = ffma2(zp[d], w.y, xp[2 * k + 1]);
        }
    }

    // FF (LN2 folded into Wff1/bff1)
    lnz_pair(xp, zp);

    if (!last) {
        #pragma unroll
        for (int j4 = 0; j4 < 16; j4++) {
            u64 t0 = *(const u64 *)(sbff1dup + j4 * 8);
            u64 t1 = *(const u64 *)(sbff1dup + j4 * 8 + 2);
            u64 t2 = *(const u64 *)(sbff1dup + j4 * 8 + 4);
            u64 t3 = *(const u64 *)(sbff1dup + j4 * 8 + 6);
            #pragma unroll
            for (int d = 0; d < 16; d++) {
                ulonglong2 wA = *(const ulonglong2 *)(sWff1dup + d * 128 + j4 * 8);
                ulonglong2 wB = *(const ulonglong2 *)(sWff1dup + d * 128 + j4 * 8 + 4);
                t0 = ffma2(zp[d], wA.x, t0); t1 = ffma2(zp[d], wA.y, t1);
                t2 = ffma2(zp[d], wB.x, t2); t3 = ffma2(zp[d], wB.y, t3);
            }
            u64 tt[4] = {t0, t1, t2, t3};
            #pragma unroll
            for (int jj = 0; jj < 4; jj++) {
                float a, c2;
                unpack2(tt[jj], a, c2);
                u64 gp = pack2(gelu_exact(a), gelu_exact(c2));
                const float *w2 = sWff2dup + (j4 * 4 + jj) * 32;
                #pragma unroll
                for (int k = 0; k < 8; k++) {
                    ulonglong2 w = *(const ulonglong2 *)(w2 + k * 4);
                    xp[2 * k]     = ffma2(gp, w.x, xp[2 * k]);
                    xp[2 * k + 1] = ffma2(gp, w.y, xp[2 * k + 1]);
                }
            }
        }
        #pragma unroll
        for (int e = 0; e < 16; e++) xp[e] = add2(xp[e], *(const u64 *)(sbff2dup + 2 * e));
        store16pair(base + n0, base + n1, valid1, xp);
        float4 rt0 = g_rot[n0];
        float4 rt1 = valid1 ? g_rot[n1] : make_float4(1, 0, 1, 0);
        u64 zq[16];
        lnz_pair(xp, zq);
        passA_pair(zq, rt0, rt1, v1, sWqNdup, sbqNdup, swqlN, sred, wid, lane);
        finish_partials(sred, b, blockIdx.x, 0);
    } else {
        float og0 = scout, og1 = scout;
        #pragma unroll
        for (int j4 = 0; j4 < 16; j4++) {
            u64 t0 = *(const u64 *)(sbff1dup + j4 * 8);
            u64 t1 = *(const u64 *)(sbff1dup + j4 * 8 + 2);
            u64 t2 = *(const u64 *)(sbff1dup + j4 * 8 + 4);
            u64 t3 = *(const u64 *)(sbff1dup + j4 * 8 + 6);
            #pragma unroll
            for (int d = 0; d < 16; d++) {
                ulonglong2 wA = *(const ulonglong2 *)(sWff1dup + d * 128 + j4 * 8);
                ulonglong2 wB = *(const ulonglong2 *)(sWff1dup + d * 128 + j4 * 8 + 4);
                t0 = ffma2(zp[d], wA.x, t0); t1 = ffma2(zp[d], wA.y, t1);
                t2 = ffma2(zp[d], wB.x, t2); t3 = ffma2(zp[d], wB.y, t3);
            }
            u64 tt[4] = {t0, t1, t2, t3};
            #pragma unroll
            for (int jj = 0; jj < 4; jj++) {
                float a, c2;
                unpack2(tt[jj], a, c2);
                float wj = sw2o[j4 * 4 + jj];
                og0 = fmaf(gelu_exact(a), wj, og0);
                og1 = fmaf(gelu_exact(c2), wj, og1);
            }
        }
        #pragma unroll
        for (int e = 0; e < 16; e++) {
            float a, c2;
            unpack2(xp[e], a, c2);
            float wd = sWout[e];
            og0 = fmaf(a, wd, og0);
            og1 = fmaf(c2, wd, og1);
        }
        out[base + n0] = og0;
        if (valid1) out[base + n1] = og1;
    }
}

// ---------------- launch ----------------
extern "C" void kernel_launch(void *const *d_in, const int *in_sizes, int n_in,
                              void *d_out, int out_size) {
    const float *corr  = (const float *)d_in[0];
    const float *Wemb  = (const float *)d_in[1];
    const float *bemb  = (const float *)d_in[2];
    const float *ln1g  = (const float *)d_in[3];
    const float *ln1b  = (const float *)d_in[4];
    const float *Wqkv  = (const float *)d_in[5];
    const float *wqlog = (const float *)d_in[6];
    const float *wklog = (const float *)d_in[7];
    const float *Wr    = (const float *)d_in[8];
    const float *br    = (const float *)d_in[9];
    const float *Wo    = (const float *)d_in[10];
    const float *bo    = (const float *)d_in[11];
    const float *ln2g  = (const float *)d_in[12];
    const float *ln2b  = (const float *)d_in[13];
    const float *Wff1  = (const float *)d_in[14];
    const float *bff1  = (const float *)d_in[15];
    const float *Wff2  = (const float *)d_in[16];
    const float *bff2  = (const float *)d_in[17];
    const float *Wout  = (const float *)d_in[18];
    const float *bout  = (const float *)d_in[19];
    float *out = (float *)d_out;
    (void)in_sizes; (void)n_in; (void)out_size;

    dim3 gridTok(NCH, NBATCH);
    k_prep<<<1, 256>>>(ln1g, ln1b, Wqkv, ln2g, ln2b, Wff1, bff1,
                       Wr, br, Wo, bo, Wff2, bff2, Wout, bout);
    k_rot<<<(NTOK + 255) / 256, 256>>>();
    k_embed<<<gridTok, TPB>>>(corr, Wemb, bemb, wqlog);
    for (int i = 0; i < LAYERS; i++) {
        k_passB<<<gridTok, TPB>>>(wklog, i);
        k_passC<<<gridTok, TPB>>>(Wff2, bff2, wqlog, Wout,
                                  out, i, i == LAYERS - 1 ? 1 : 0);
    }
}